// round 11
// baseline (speedup 1.0000x reference)
#include <cuda_runtime.h>
#include <cuda_fp16.h>
#include <cstdint>

// ---------------- problem constants ----------------
#define NB    64
#define CIN   3
#define HIN   224
#define CH    96
#define HH    56
#define SH    3136    // 56*56
#define HO    14
#define SPA   196
#define MM2   12544   // GEMM M
#define KDIM  1536    // GEMM K
#define ND    768     // GEMM N
#define NOFF  32

// ---------------- scratch (device globals) ----------------
__device__ __half g_hh[(size_t)NB*HH*HH*CH];   // stem output fp16 NHWC
__device__ float  g_off[(size_t)MM2*NOFF];     // offsets [m][32]
__device__ __half g_woh[(size_t)NOFF*KDIM];    // off_w [n][k*96+c] fp16
__device__ __half g_Af [(size_t)MM2*KDIM];     // sampled A, fp16
__device__ __half g_Bhi[(size_t)ND*KDIM];      // dcn_w [o][k*96+c] fp16

// ==================== PTX helpers (plain-target safe) ====================
__device__ __forceinline__ uint32_t smem_to_u32(const void* p) {
    uint32_t a;
    asm("{ .reg .u64 t; cvta.to.shared.u64 t, %1; cvt.u32.u64 %0, t; }" : "=r"(a) : "l"(p));
    return a;
}
#define CP_ASYNC16(s, g) \
    asm volatile("cp.async.cg.shared.global [%0], [%1], 16;" :: "r"(s), "l"(g) : "memory")
#define CP_COMMIT() asm volatile("cp.async.commit_group;" ::: "memory")
#define LDSM4(r, a) \
    asm volatile("ldmatrix.sync.aligned.m8n8.x4.shared.b16 {%0,%1,%2,%3}, [%4];" \
        : "=r"((r)[0]), "=r"((r)[1]), "=r"((r)[2]), "=r"((r)[3]) : "r"(a))
#define MMA16816(d, a, b0v, b1v) \
    asm volatile("mma.sync.aligned.m16n8k16.row.col.f32.f16.f16.f32 " \
        "{%0,%1,%2,%3},{%4,%5,%6,%7},{%8,%9},{%0,%1,%2,%3};" \
        : "+f"((d)[0]), "+f"((d)[1]), "+f"((d)[2]), "+f"((d)[3]) \
        : "r"((a)[0]), "r"((a)[1]), "r"((a)[2]), "r"((a)[3]), "r"(b0v), "r"(b1v))

// =====================================================================
// Kernel 1: stem patchify GEMM via mma.sync (M=200704, N=96, K=48)
// =====================================================================
#define SMEM_ST (16384 + 12288 + 1024)

__global__ __launch_bounds__(128) void stem_mma_kernel(
    const float* __restrict__ x, const float* __restrict__ w,
    const float* __restrict__ bias,
    const float* __restrict__ g1, const float* __restrict__ b1,
    const float* __restrict__ m1, const float* __restrict__ v1)
{
    extern __shared__ char smem[];
    uint32_t sb = smem_to_u32(smem);
    char* sA = smem;
    char* sB = smem + 16384;
    float* sScale = (float*)(smem + 28672);
    float* sBeta  = (float*)(smem + 28672 + 512);
    int tid = threadIdx.x, lane = tid & 31, wid = tid >> 5;
    int bm = blockIdx.x * 128;

    if (tid < CH) {
        float inv = g1[tid] * rsqrtf(v1[tid] + 1e-5f);
        sScale[tid] = inv;
        sBeta[tid]  = (bias[tid] - m1[tid]) * inv + b1[tid];
    }

    #pragma unroll
    for (int i = 0; i < 5; i++) {
        int tsk = tid + i*128;
        if (tsk < 576) {
            int o = tsk / 6, jj = tsk % 6;
            const float* wp = w + o*48 + jj*8;
            float4 f0 = *(const float4*)wp;
            float4 f1 = *(const float4*)(wp + 4);
            __half2 h0 = __floats2half2_rn(f0.x, f0.y);
            __half2 h1 = __floats2half2_rn(f0.z, f0.w);
            __half2 h2 = __floats2half2_rn(f1.x, f1.y);
            __half2 h3 = __floats2half2_rn(f1.z, f1.w);
            uint4 u;
            u.x = *(uint32_t*)&h0; u.y = *(uint32_t*)&h1;
            u.z = *(uint32_t*)&h2; u.w = *(uint32_t*)&h3;
            *(uint4*)(sB + o*128 + ((jj ^ (o & 7)) << 4)) = u;
        }
    }

    #pragma unroll
    for (int i = 0; i < 6; i++) {
        int tsk = tid + i*128;
        int jj = tsk >> 7, r = tsk & 127;
        int m = bm + r;
        int b = m / SH, s = m % SH;
        int oh = s / HH, ow = s % HH;
        int p0 = 2*jj, p1 = p0 + 1;
        const float* x0 = x + ((size_t)(b*CIN + (p0 >> 2))*HIN + 4*oh + (p0 & 3))*HIN + 4*ow;
        const float* x1 = x + ((size_t)(b*CIN + (p1 >> 2))*HIN + 4*oh + (p1 & 3))*HIN + 4*ow;
        float4 f0 = *(const float4*)x0;
        float4 f1 = *(const float4*)x1;
        __half2 h0 = __floats2half2_rn(f0.x, f0.y);
        __half2 h1 = __floats2half2_rn(f0.z, f0.w);
        __half2 h2 = __floats2half2_rn(f1.x, f1.y);
        __half2 h3 = __floats2half2_rn(f1.z, f1.w);
        uint4 u;
        u.x = *(uint32_t*)&h0; u.y = *(uint32_t*)&h1;
        u.z = *(uint32_t*)&h2; u.w = *(uint32_t*)&h3;
        *(uint4*)(sA + r*128 + ((jj ^ (r & 7)) << 4)) = u;
    }
    __syncthreads();

    float acc[2][12][4];
    #pragma unroll
    for (int i = 0; i < 2; i++)
        #pragma unroll
        for (int j = 0; j < 12; j++)
            #pragma unroll
            for (int q = 0; q < 4; q++) acc[i][j][q] = 0.f;

    int lrow = lane & 15, lc = lane >> 4;
    #pragma unroll
    for (int g = 0; g < 3; g++) {
        int ch = g*2 + lc;
        uint32_t a[2][4];
        #pragma unroll
        for (int mi = 0; mi < 2; mi++) {
            int row = wid*32 + mi*16 + lrow;
            LDSM4(a[mi], sb + (uint32_t)(row*128 + (((ch ^ (row & 7))) << 4)));
        }
        #pragma unroll
        for (int nb = 0; nb < 6; nb++) {
            int rowb = nb*16 + lrow;
            uint32_t bh[4];
            LDSM4(bh, sb + 16384u + (uint32_t)(rowb*128 + (((ch ^ (rowb & 7))) << 4)));
            #pragma unroll
            for (int mi = 0; mi < 2; mi++) {
                MMA16816(acc[mi][2*nb],   a[mi], bh[0], bh[2]);
                MMA16816(acc[mi][2*nb+1], a[mi], bh[1], bh[3]);
            }
        }
    }

    #pragma unroll
    for (int mi = 0; mi < 2; mi++) {
        int r0 = bm + wid*32 + mi*16 + (lane >> 2);
        #pragma unroll
        for (int nj = 0; nj < 12; nj++) {
            int col = nj*8 + (lane & 3)*2;
            float s0 = sScale[col], s1 = sScale[col+1];
            float e0 = sBeta[col],  e1 = sBeta[col+1];
            float v0 = acc[mi][nj][0]*s0 + e0;
            float v1 = acc[mi][nj][1]*s1 + e1;
            float v2 = acc[mi][nj][2]*s0 + e0;
            float v3 = acc[mi][nj][3]*s1 + e1;
            v0 = (v0 >= 0.f) ? v0 : 0.01f*v0;
            v1 = (v1 >= 0.f) ? v1 : 0.01f*v1;
            v2 = (v2 >= 0.f) ? v2 : 0.01f*v2;
            v3 = (v3 >= 0.f) ? v3 : 0.01f*v3;
            __half2 ha = __floats2half2_rn(v0, v1);
            __half2 hbv = __floats2half2_rn(v2, v3);
            *(__half2*)&g_hh[(size_t)r0*CH + col]     = ha;
            *(__half2*)&g_hh[(size_t)(r0+8)*CH + col] = hbv;
        }
    }
}

// =====================================================================
// Kernel 2: weight prep (dcn_w fp16, off_w fp16, both [n][k*96+c])
// =====================================================================
__global__ __launch_bounds__(256) void prep_kernel(
    const float* __restrict__ wd, const float* __restrict__ wo)
{
    int i = blockIdx.x*256 + threadIdx.x;
    if (i < ND*KDIM) {
        int o = i / KDIM, r = i % KDIM;
        int k = r / CH, c = r % CH;
        g_Bhi[i] = __float2half(wd[(size_t)o*KDIM + c*16 + k]);
    }
    if (i < NOFF*KDIM) {
        int n = i / KDIM, r = i % KDIM;
        int k = r / CH, c = r % CH;
        g_woh[i] = __float2half(wo[(size_t)n*KDIM + c*16 + k]);
    }
}

// =====================================================================
// Kernel 3: offset conv via mma.sync, single-pass fp16 (M-tile 32)
// =====================================================================
#define OC_NIT 48
#define OC_STG 4096u     // A 2K | W 2K
#define SMEM_OC (4*OC_STG)

__global__ __launch_bounds__(64, 4) void offconv_mma_kernel(const float* __restrict__ offb)
{
    extern __shared__ char smem[];
    uint32_t sb = smem_to_u32(smem);
    int tid = threadIdx.x;
    int lane = tid & 31, wid = tid >> 5;
    int bm = blockIdx.x * 32;

    int c4 = tid & 3;
    int ar0 = tid >> 2, ar1 = ar0 + 16;
    size_t rb[2];
    uint32_t sa_off[2];
    #pragma unroll
    for (int i = 0; i < 2; i++) {
        int r = (i == 0) ? ar0 : ar1;
        int m = bm + r;
        int b = m / SPA, s = m % SPA;
        rb[i] = ((size_t)(b*HH + (s/HO)*4)*HH + (s%HO)*4)*CH;
        sa_off[i] = (uint32_t)(r*64 + ((c4 ^ ((r>>1)&3))*16));
    }

    auto load_stage = [&](int stg, int kt) {
        uint32_t base = sb + (uint32_t)stg * OC_STG;
        int kpix = kt / 3;
        int poff = (kpix >> 2)*(HH*CH) + (kpix & 3)*CH + (kt - kpix*3)*32 + c4*8;
        CP_ASYNC16(base + sa_off[0], g_hh + rb[0] + poff);
        CP_ASYNC16(base + sa_off[1], g_hh + rb[1] + poff);
        CP_ASYNC16(base + 2048 + sa_off[0], g_woh + (size_t)ar0*KDIM + kt*32 + c4*8);
        CP_ASYNC16(base + 2048 + sa_off[1], g_woh + (size_t)ar1*KDIM + kt*32 + c4*8);
        CP_COMMIT();
    };

    int lrow = lane & 15, lc = lane >> 4;
    uint32_t a_off[2], w_off[2][2];
    #pragma unroll
    for (int kh = 0; kh < 2; kh++) {
        int row = wid*16 + lrow;
        a_off[kh] = (uint32_t)(row*64 + (((kh*2 + lc) ^ ((row>>1)&3))*16));
        #pragma unroll
        for (int h = 0; h < 2; h++) {
            int wr2 = h*16 + lrow;
            w_off[h][kh] = (uint32_t)(wr2*64 + (((kh*2 + lc) ^ ((wr2>>1)&3))*16));
        }
    }

    float acc[4][4];
    #pragma unroll
    for (int i = 0; i < 4; i++)
        #pragma unroll
        for (int q = 0; q < 4; q++) acc[i][q] = 0.f;

    load_stage(0, 0); load_stage(1, 1); load_stage(2, 2);

    for (int kt = 0; kt < OC_NIT; kt++) {
        if (kt + 2 < OC_NIT) asm volatile("cp.async.wait_group 2;" ::: "memory");
        else                 asm volatile("cp.async.wait_group 0;" ::: "memory");
        __syncthreads();
        if (kt + 3 < OC_NIT) load_stage((kt+3) & 3, kt+3);

        uint32_t base = sb + (uint32_t)(kt & 3) * OC_STG;
        #pragma unroll
        for (int kh = 0; kh < 2; kh++) {
            uint32_t ah[4];
            LDSM4(ah, base + a_off[kh]);
            #pragma unroll
            for (int h = 0; h < 2; h++) {
                uint32_t wh[4];
                LDSM4(wh, base + 2048 + w_off[h][kh]);
                MMA16816(acc[h*2],   ah, wh[0], wh[2]);
                MMA16816(acc[h*2+1], ah, wh[1], wh[3]);
            }
        }
    }

    int rr = bm + wid*16 + (lane >> 2);
    #pragma unroll
    for (int nj = 0; nj < 4; nj++) {
        int col = (nj >> 1)*16 + (nj & 1)*8 + (lane & 3)*2;
        float b0v = offb[col], b1v = offb[col+1];
        *(float2*)&g_off[(size_t)rr*NOFF + col] =
            make_float2(acc[nj][0] + b0v, acc[nj][1] + b1v);
        *(float2*)&g_off[(size_t)(rr+8)*NOFF + col] =
            make_float2(acc[nj][2] + b0v, acc[nj][3] + b1v);
    }
}

// =====================================================================
// Kernel 4: bilinear sampling — SOFTWARE-PIPELINED gathers
// One warp per m; lanes 0-15 prologue; loop prefetches k+1's shfl+loads
// before computing k, hiding L2 gather latency behind compute+store.
// =====================================================================
__global__ __launch_bounds__(256) void sample_kernel()
{
    int m    = (blockIdx.x*256 + threadIdx.x) >> 5;
    int lane = threadIdx.x & 31;
    int b = m / SPA, s = m % SPA;
    int oh = s / HO, ow = s % HO;

    int e00 = 0, e01 = 0, e10 = 0, e11 = 0;
    uint32_t uq00 = 0, uq01 = 0, uq10 = 0, uq11 = 0;
    if (lane < 16) {
        int k = lane;
        float offy = g_off[(size_t)m*NOFF + k*2];
        float offx = g_off[(size_t)m*NOFF + k*2 + 1];
        float py = (float)(oh*4 + (k >> 2)) + offy;
        float px = (float)(ow*4 + (k & 3)) + offx;
        float y0f = floorf(py), x0f = floorf(px);
        float wy = py - y0f, wx = px - x0f;
        int y0 = (int)y0f, x0 = (int)x0f;
        int y1 = y0 + 1,  x1 = x0 + 1;
        bool vy0 = (y0 >= 0) & (y0 < HH), vy1 = (y1 >= 0) & (y1 < HH);
        bool vx0 = (x0 >= 0) & (x0 < HH), vx1 = (x1 >= 0) & (x1 < HH);
        int cy0 = min(max(y0, 0), HH-1), cy1 = min(max(y1, 0), HH-1);
        int cx0 = min(max(x0, 0), HH-1), cx1 = min(max(x1, 0), HH-1);
        e00 = (cy0*HH + cx0)*CH;
        e01 = (cy0*HH + cx1)*CH;
        e10 = (cy1*HH + cx0)*CH;
        e11 = (cy1*HH + cx1)*CH;
        float w00 = (1.f-wy)*(1.f-wx) * (float)(vy0 && vx0);
        float w01 = (1.f-wy)*wx       * (float)(vy0 && vx1);
        float w10 = wy*(1.f-wx)       * (float)(vy1 && vx0);
        float w11 = wy*wx             * (float)(vy1 && vx1);
        __half2 h;
        h = __floats2half2_rn(w00, w00); uq00 = *(uint32_t*)&h;
        h = __floats2half2_rn(w01, w01); uq01 = *(uint32_t*)&h;
        h = __floats2half2_rn(w10, w10); uq10 = *(uint32_t*)&h;
        h = __floats2half2_rn(w11, w11); uq11 = *(uint32_t*)&h;
    }

    const __half* hb = g_hh + (size_t)b*HH*HH*CH;
    __half* ob = g_Af + (size_t)m*KDIM;
    bool act = (lane < 12);
    int c = act ? lane*8 : 0;

    uint4 u00, u01, u10, u11;
    uint32_t p00, p01, p10, p11;
    {   // fetch k=0
        int f00 = __shfl_sync(0xFFFFFFFFu, e00, 0);
        int f01 = __shfl_sync(0xFFFFFFFFu, e01, 0);
        int f10 = __shfl_sync(0xFFFFFFFFu, e10, 0);
        int f11 = __shfl_sync(0xFFFFFFFFu, e11, 0);
        p00 = __shfl_sync(0xFFFFFFFFu, uq00, 0);
        p01 = __shfl_sync(0xFFFFFFFFu, uq01, 0);
        p10 = __shfl_sync(0xFFFFFFFFu, uq10, 0);
        p11 = __shfl_sync(0xFFFFFFFFu, uq11, 0);
        if (act) {
            u00 = *(const uint4*)(hb + f00 + c);
            u01 = *(const uint4*)(hb + f01 + c);
            u10 = *(const uint4*)(hb + f10 + c);
            u11 = *(const uint4*)(hb + f11 + c);
        }
    }

    #pragma unroll
    for (int k = 0; k < 16; k++) {
        uint4 n00, n01, n10, n11;
        uint32_t q00n = 0, q01n = 0, q10n = 0, q11n = 0;
        if (k < 15) {   // prefetch k+1 BEFORE consuming k
            int f00 = __shfl_sync(0xFFFFFFFFu, e00, k+1);
            int f01 = __shfl_sync(0xFFFFFFFFu, e01, k+1);
            int f10 = __shfl_sync(0xFFFFFFFFu, e10, k+1);
            int f11 = __shfl_sync(0xFFFFFFFFu, e11, k+1);
            q00n = __shfl_sync(0xFFFFFFFFu, uq00, k+1);
            q01n = __shfl_sync(0xFFFFFFFFu, uq01, k+1);
            q10n = __shfl_sync(0xFFFFFFFFu, uq10, k+1);
            q11n = __shfl_sync(0xFFFFFFFFu, uq11, k+1);
            if (act) {
                n00 = *(const uint4*)(hb + f00 + c);
                n01 = *(const uint4*)(hb + f01 + c);
                n10 = *(const uint4*)(hb + f10 + c);
                n11 = *(const uint4*)(hb + f11 + c);
            }
        }
        if (act) {
            __half2 q00 = *(__half2*)&p00, q01 = *(__half2*)&p01;
            __half2 q10 = *(__half2*)&p10, q11 = *(__half2*)&p11;
            const uint32_t* a4 = &u00.x;
            const uint32_t* b4 = &u01.x;
            const uint32_t* c4 = &u10.x;
            const uint32_t* d4 = &u11.x;
            uint4 o;
            uint32_t* o4 = &o.x;
            #pragma unroll
            for (int t = 0; t < 4; t++) {
                __half2 r = __hmul2(*(const __half2*)&a4[t], q00);
                r = __hfma2(*(const __half2*)&b4[t], q01, r);
                r = __hfma2(*(const __half2*)&c4[t], q10, r);
                r = __hfma2(*(const __half2*)&d4[t], q11, r);
                o4[t] = *(uint32_t*)&r;
            }
            *(uint4*)(ob + k*CH + c) = o;
        }
        if (k < 15) {
            u00 = n00; u01 = n01; u10 = n10; u11 = n11;
            p00 = q00n; p01 = q01n; p10 = q10n; p11 = q11n;
        }
    }
}

// =====================================================================
// Kernel 5: single-pass fp16 GEMM + BN2 + LeakyReLU
// CTA 128x256, BK=64, 8 warps (warp 64x64, 2x4 grid), 2-stage, 1 CTA/SM
// SMEM stage: A 16K | B 32K = 48K; reads/output halved vs 128x128
// =====================================================================
#define BK       64
#define NIT      24
#define OFF_B    16384u
#define STG_BYTES 49152u
#define NSTAGE   2
#define SMEM_GEMM (NSTAGE*STG_BYTES + 2048)

__global__ __launch_bounds__(256, 1) void gemm_mma_kernel(
    const float* __restrict__ dcnb, const float* __restrict__ g2,
    const float* __restrict__ b2,   const float* __restrict__ bn2m,
    const float* __restrict__ v2,   float* __restrict__ out)
{
    extern __shared__ char smem[];
    uint32_t sb = smem_to_u32(smem);
    float* sScale = (float*)(smem + NSTAGE*STG_BYTES);
    float* sBeta  = sScale + 256;

    int tid  = threadIdx.x;
    int lane = tid & 31, wid = tid >> 5;
    int wm = wid & 1, wn = wid >> 1;      // warp 64x64, 2x4 grid
    int bm = blockIdx.y * 128;
    int bn = blockIdx.x * 256;

    {
        int n = bn + tid;
        float inv = g2[n] * rsqrtf(v2[n] + 1e-5f);
        sScale[tid] = inv;
        sBeta[tid]  = (dcnb[n] - bn2m[n])*inv + b2[n];
    }

    auto load_stage = [&](int stg, int kt) {
        uint32_t base = sb + (uint32_t)stg * STG_BYTES;
        int ks = kt * BK;
        #pragma unroll
        for (int i = 0; i < 4; i++) {             // A: 1024 chunks
            int id = tid + i*256;
            int row = id >> 3, c = id & 7;
            uint32_t so = (uint32_t)(row*128 + ((c ^ (row & 7))*16));
            CP_ASYNC16(base + so, g_Af + (size_t)(bm+row)*KDIM + ks + c*8);
        }
        #pragma unroll
        for (int i = 0; i < 8; i++) {             // B: 2048 chunks
            int id = tid + i*256;
            int row = id >> 3, c = id & 7;
            uint32_t so = (uint32_t)(row*128 + ((c ^ (row & 7))*16));
            CP_ASYNC16(base + OFF_B + so, g_Bhi + (size_t)(bn+row)*KDIM + ks + c*8);
        }
        CP_COMMIT();
    };

    int lrow = lane & 15, lc = lane >> 4;
    uint32_t a_base[4]; int a_rs[4];
    uint32_t b_base[4]; int b_rs[4];
    #pragma unroll
    for (int mi = 0; mi < 4; mi++) {
        int row = wm*64 + mi*16 + lrow;
        a_base[mi] = (uint32_t)(row*128);
        a_rs[mi]   = row & 7;
    }
    #pragma unroll
    for (int nb = 0; nb < 4; nb++) {
        int row = wn*64 + nb*16 + lrow;
        b_base[nb] = (uint32_t)(row*128);
        b_rs[nb]   = row & 7;
    }

    float acc[4][8][4];
    #pragma unroll
    for (int i = 0; i < 4; i++)
        #pragma unroll
        for (int j = 0; j < 8; j++)
            #pragma unroll
            for (int q = 0; q < 4; q++) acc[i][j][q] = 0.f;

    load_stage(0, 0); load_stage(1, 1);

    for (int kt = 0; kt < NIT; kt++) {
        if (kt + 1 < NIT) asm volatile("cp.async.wait_group 1;" ::: "memory");
        else              asm volatile("cp.async.wait_group 0;" ::: "memory");
        __syncthreads();

        uint32_t base = sb + (uint32_t)(kt & 1) * STG_BYTES;
        #pragma unroll
        for (int kh = 0; kh < 4; kh++) {
            int ch = kh*2 + lc;
            uint32_t a[4][4];
            #pragma unroll
            for (int mi = 0; mi < 4; mi++)
                LDSM4(a[mi], base + a_base[mi] + (uint32_t)(((ch ^ a_rs[mi]) << 4)));
            #pragma unroll
            for (int nb = 0; nb < 4; nb++) {
                uint32_t bh[4];
                LDSM4(bh, base + OFF_B + b_base[nb] + (uint32_t)(((ch ^ b_rs[nb]) << 4)));
                #pragma unroll
                for (int mi = 0; mi < 4; mi++) {
                    MMA16816(acc[mi][2*nb],   a[mi], bh[0], bh[2]);
                    MMA16816(acc[mi][2*nb+1], a[mi], bh[1], bh[3]);
                }
            }
        }
        __syncthreads();    // all warps done reading buffer (kt&1)
        if (kt + 2 < NIT) load_stage(kt & 1, kt + 2);
    }

    #pragma unroll
    for (int mi = 0; mi < 4; mi++) {
        int r0 = bm + wm*64 + mi*16 + (lane >> 2);
        #pragma unroll
        for (int nj = 0; nj < 8; nj++) {
            int colL = wn*64 + nj*8 + (lane & 3)*2;
            float s0 = sScale[colL],   s1 = sScale[colL+1];
            float e0 = sBeta[colL],    e1 = sBeta[colL+1];
            float v0 = acc[mi][nj][0]*s0 + e0;
            float v1 = acc[mi][nj][1]*s1 + e1;
            float v2 = acc[mi][nj][2]*s0 + e0;
            float v3 = acc[mi][nj][3]*s1 + e1;
            v0 = (v0 >= 0.f) ? v0 : 0.01f*v0;
            v1 = (v1 >= 0.f) ? v1 : 0.01f*v1;
            v2 = (v2 >= 0.f) ? v2 : 0.01f*v2;
            v3 = (v3 >= 0.f) ? v3 : 0.01f*v3;
            *(float2*)&out[(size_t)r0*ND + bn + colL]     = make_float2(v0, v1);
            *(float2*)&out[(size_t)(r0+8)*ND + bn + colL] = make_float2(v2, v3);
        }
    }
}

// =====================================================================
extern "C" void kernel_launch(void* const* d_in, const int* in_sizes, int n_in,
                              void* d_out, int out_size)
{
    const float* x      = (const float*)d_in[0];
    const float* stem_w = (const float*)d_in[1];
    const float* stem_b = (const float*)d_in[2];
    const float* bn1_g  = (const float*)d_in[3];
    const float* bn1_b  = (const float*)d_in[4];
    const float* bn1_m  = (const float*)d_in[5];
    const float* bn1_v  = (const float*)d_in[6];
    const float* off_w  = (const float*)d_in[7];
    const float* off_b  = (const float*)d_in[8];
    const float* dcn_w  = (const float*)d_in[9];
    const float* dcn_b  = (const float*)d_in[10];
    const float* bn2_g  = (const float*)d_in[11];
    const float* bn2_b  = (const float*)d_in[12];
    const float* bn2_m  = (const float*)d_in[13];
    const float* bn2_v  = (const float*)d_in[14];
    float* out = (float*)d_out;

    cudaFuncSetAttribute(gemm_mma_kernel,
                         cudaFuncAttributeMaxDynamicSharedMemorySize, SMEM_GEMM);
    cudaFuncSetAttribute(offconv_mma_kernel,
                         cudaFuncAttributeMaxDynamicSharedMemorySize, SMEM_OC);
    cudaFuncSetAttribute(stem_mma_kernel,
                         cudaFuncAttributeMaxDynamicSharedMemorySize, SMEM_ST);

    stem_mma_kernel<<<(NB*SH)/128, 128, SMEM_ST>>>(
        x, stem_w, stem_b, bn1_g, bn1_b, bn1_m, bn1_v);
    prep_kernel<<<(ND*KDIM + 255)/256, 256>>>(dcn_w, off_w);
    offconv_mma_kernel<<<MM2/32, 64, SMEM_OC>>>(off_b);
    sample_kernel<<<MM2*32/256, 256>>>();
    gemm_mma_kernel<<<dim3(ND/256, MM2/128), 256, SMEM_GEMM>>>(
        dcn_b, bn2_g, bn2_b, bn2_m, bn2_v, out);
}

// round 12
// speedup vs baseline: 1.0414x; 1.0414x over previous
#include <cuda_runtime.h>
#include <cuda_fp16.h>
#include <cstdint>

// ---------------- problem constants ----------------
#define NB    64
#define CIN   3
#define HIN   224
#define CH    96
#define HH    56
#define SH    3136    // 56*56
#define HO    14
#define SPA   196
#define MM2   12544   // GEMM M
#define KDIM  1536    // GEMM K
#define ND    768     // GEMM N
#define NOFF  32
#define NSTEM 1568    // stem blocks; blocks beyond do weight prep

// ---------------- scratch (device globals) ----------------
__device__ __half g_hh[(size_t)NB*HH*HH*CH];   // stem output fp16 NHWC
__device__ float  g_off[(size_t)MM2*NOFF];     // offsets [m][32]
__device__ __half g_woh[(size_t)NOFF*KDIM];    // off_w [n][k*96+c] fp16
__device__ __half g_Af [(size_t)MM2*KDIM];     // sampled A, fp16
__device__ __half g_Bhi[(size_t)ND*KDIM];      // dcn_w [o][k*96+c] fp16

// ==================== PTX helpers (plain-target safe) ====================
__device__ __forceinline__ uint32_t smem_to_u32(const void* p) {
    uint32_t a;
    asm("{ .reg .u64 t; cvta.to.shared.u64 t, %1; cvt.u32.u64 %0, t; }" : "=r"(a) : "l"(p));
    return a;
}
#define CP_ASYNC16(s, g) \
    asm volatile("cp.async.cg.shared.global [%0], [%1], 16;" :: "r"(s), "l"(g) : "memory")
#define CP_COMMIT() asm volatile("cp.async.commit_group;" ::: "memory")
#define LDSM4(r, a) \
    asm volatile("ldmatrix.sync.aligned.m8n8.x4.shared.b16 {%0,%1,%2,%3}, [%4];" \
        : "=r"((r)[0]), "=r"((r)[1]), "=r"((r)[2]), "=r"((r)[3]) : "r"(a))
#define MMA16816(d, a, b0v, b1v) \
    asm volatile("mma.sync.aligned.m16n8k16.row.col.f32.f16.f16.f32 " \
        "{%0,%1,%2,%3},{%4,%5,%6,%7},{%8,%9},{%0,%1,%2,%3};" \
        : "+f"((d)[0]), "+f"((d)[1]), "+f"((d)[2]), "+f"((d)[3]) \
        : "r"((a)[0]), "r"((a)[1]), "r"((a)[2]), "r"((a)[3]), "r"(b0v), "r"(b1v))

// =====================================================================
// Kernel 1: stem patchify GEMM via mma.sync + fused weight prep blocks
// Blocks [0, NSTEM): stem tile. Blocks >= NSTEM: dcn_w/off_w fp16 prep.
// =====================================================================
#define SMEM_ST (16384 + 12288 + 1024)
#define PREP_BLKS 1152    // 1152*1024 >= 768*1536

__global__ __launch_bounds__(128) void stem_mma_kernel(
    const float* __restrict__ x, const float* __restrict__ w,
    const float* __restrict__ bias,
    const float* __restrict__ g1, const float* __restrict__ b1,
    const float* __restrict__ m1, const float* __restrict__ v1,
    const float* __restrict__ wd, const float* __restrict__ wo)
{
    int tid = threadIdx.x;

    // ---------------- weight-prep blocks ----------------
    if (blockIdx.x >= NSTEM) {
        int pb = blockIdx.x - NSTEM;
        #pragma unroll
        for (int i = 0; i < 8; i++) {
            int idx = pb*1024 + i*128 + tid;
            if (idx < ND*KDIM) {
                int o = idx / KDIM, r = idx % KDIM;
                int k = r / CH, c = r % CH;
                g_Bhi[idx] = __float2half(wd[(size_t)o*KDIM + c*16 + k]);
            }
            if (idx < NOFF*KDIM) {
                int n = idx / KDIM, r = idx % KDIM;
                int k = r / CH, c = r % CH;
                g_woh[idx] = __float2half(wo[(size_t)n*KDIM + c*16 + k]);
            }
        }
        return;
    }

    // ---------------- stem tile blocks ----------------
    extern __shared__ char smem[];
    uint32_t sb = smem_to_u32(smem);
    char* sA = smem;
    char* sB = smem + 16384;
    float* sScale = (float*)(smem + 28672);
    float* sBeta  = (float*)(smem + 28672 + 512);
    int lane = tid & 31, wid = tid >> 5;
    int bm = blockIdx.x * 128;

    if (tid < CH) {
        float inv = g1[tid] * rsqrtf(v1[tid] + 1e-5f);
        sScale[tid] = inv;
        sBeta[tid]  = (bias[tid] - m1[tid]) * inv + b1[tid];
    }

    #pragma unroll
    for (int i = 0; i < 5; i++) {
        int tsk = tid + i*128;
        if (tsk < 576) {
            int o = tsk / 6, jj = tsk % 6;
            const float* wp = w + o*48 + jj*8;
            float4 f0 = *(const float4*)wp;
            float4 f1 = *(const float4*)(wp + 4);
            __half2 h0 = __floats2half2_rn(f0.x, f0.y);
            __half2 h1 = __floats2half2_rn(f0.z, f0.w);
            __half2 h2 = __floats2half2_rn(f1.x, f1.y);
            __half2 h3 = __floats2half2_rn(f1.z, f1.w);
            uint4 u;
            u.x = *(uint32_t*)&h0; u.y = *(uint32_t*)&h1;
            u.z = *(uint32_t*)&h2; u.w = *(uint32_t*)&h3;
            *(uint4*)(sB + o*128 + ((jj ^ (o & 7)) << 4)) = u;
        }
    }

    #pragma unroll
    for (int i = 0; i < 6; i++) {
        int tsk = tid + i*128;
        int jj = tsk >> 7, r = tsk & 127;
        int m = bm + r;
        int b = m / SH, s = m % SH;
        int oh = s / HH, ow = s % HH;
        int p0 = 2*jj, p1 = p0 + 1;
        const float* x0 = x + ((size_t)(b*CIN + (p0 >> 2))*HIN + 4*oh + (p0 & 3))*HIN + 4*ow;
        const float* x1 = x + ((size_t)(b*CIN + (p1 >> 2))*HIN + 4*oh + (p1 & 3))*HIN + 4*ow;
        float4 f0 = *(const float4*)x0;
        float4 f1 = *(const float4*)x1;
        __half2 h0 = __floats2half2_rn(f0.x, f0.y);
        __half2 h1 = __floats2half2_rn(f0.z, f0.w);
        __half2 h2 = __floats2half2_rn(f1.x, f1.y);
        __half2 h3 = __floats2half2_rn(f1.z, f1.w);
        uint4 u;
        u.x = *(uint32_t*)&h0; u.y = *(uint32_t*)&h1;
        u.z = *(uint32_t*)&h2; u.w = *(uint32_t*)&h3;
        *(uint4*)(sA + r*128 + ((jj ^ (r & 7)) << 4)) = u;
    }
    __syncthreads();

    float acc[2][12][4];
    #pragma unroll
    for (int i = 0; i < 2; i++)
        #pragma unroll
        for (int j = 0; j < 12; j++)
            #pragma unroll
            for (int q = 0; q < 4; q++) acc[i][j][q] = 0.f;

    int lrow = lane & 15, lc = lane >> 4;
    #pragma unroll
    for (int g = 0; g < 3; g++) {
        int ch = g*2 + lc;
        uint32_t a[2][4];
        #pragma unroll
        for (int mi = 0; mi < 2; mi++) {
            int row = wid*32 + mi*16 + lrow;
            LDSM4(a[mi], sb + (uint32_t)(row*128 + (((ch ^ (row & 7))) << 4)));
        }
        #pragma unroll
        for (int nb = 0; nb < 6; nb++) {
            int rowb = nb*16 + lrow;
            uint32_t bh[4];
            LDSM4(bh, sb + 16384u + (uint32_t)(rowb*128 + (((ch ^ (rowb & 7))) << 4)));
            #pragma unroll
            for (int mi = 0; mi < 2; mi++) {
                MMA16816(acc[mi][2*nb],   a[mi], bh[0], bh[2]);
                MMA16816(acc[mi][2*nb+1], a[mi], bh[1], bh[3]);
            }
        }
    }

    #pragma unroll
    for (int mi = 0; mi < 2; mi++) {
        int r0 = bm + wid*32 + mi*16 + (lane >> 2);
        #pragma unroll
        for (int nj = 0; nj < 12; nj++) {
            int col = nj*8 + (lane & 3)*2;
            float s0 = sScale[col], s1 = sScale[col+1];
            float e0 = sBeta[col],  e1 = sBeta[col+1];
            float v0 = acc[mi][nj][0]*s0 + e0;
            float v1 = acc[mi][nj][1]*s1 + e1;
            float v2 = acc[mi][nj][2]*s0 + e0;
            float v3 = acc[mi][nj][3]*s1 + e1;
            v0 = (v0 >= 0.f) ? v0 : 0.01f*v0;
            v1 = (v1 >= 0.f) ? v1 : 0.01f*v1;
            v2 = (v2 >= 0.f) ? v2 : 0.01f*v2;
            v3 = (v3 >= 0.f) ? v3 : 0.01f*v3;
            __half2 ha = __floats2half2_rn(v0, v1);
            __half2 hbv = __floats2half2_rn(v2, v3);
            *(__half2*)&g_hh[(size_t)r0*CH + col]     = ha;
            *(__half2*)&g_hh[(size_t)(r0+8)*CH + col] = hbv;
        }
    }
}

// =====================================================================
// Kernel 3: offset conv via mma.sync, single-pass fp16 (M-tile 32)
// =====================================================================
#define OC_NIT 48
#define OC_STG 4096u     // A 2K | W 2K
#define SMEM_OC (4*OC_STG)

__global__ __launch_bounds__(64, 4) void offconv_mma_kernel(const float* __restrict__ offb)
{
    extern __shared__ char smem[];
    uint32_t sb = smem_to_u32(smem);
    int tid = threadIdx.x;
    int lane = tid & 31, wid = tid >> 5;
    int bm = blockIdx.x * 32;

    int c4 = tid & 3;
    int ar0 = tid >> 2, ar1 = ar0 + 16;
    size_t rb[2];
    uint32_t sa_off[2];
    #pragma unroll
    for (int i = 0; i < 2; i++) {
        int r = (i == 0) ? ar0 : ar1;
        int m = bm + r;
        int b = m / SPA, s = m % SPA;
        rb[i] = ((size_t)(b*HH + (s/HO)*4)*HH + (s%HO)*4)*CH;
        sa_off[i] = (uint32_t)(r*64 + ((c4 ^ ((r>>1)&3))*16));
    }

    auto load_stage = [&](int stg, int kt) {
        uint32_t base = sb + (uint32_t)stg * OC_STG;
        int kpix = kt / 3;
        int poff = (kpix >> 2)*(HH*CH) + (kpix & 3)*CH + (kt - kpix*3)*32 + c4*8;
        CP_ASYNC16(base + sa_off[0], g_hh + rb[0] + poff);
        CP_ASYNC16(base + sa_off[1], g_hh + rb[1] + poff);
        CP_ASYNC16(base + 2048 + sa_off[0], g_woh + (size_t)ar0*KDIM + kt*32 + c4*8);
        CP_ASYNC16(base + 2048 + sa_off[1], g_woh + (size_t)ar1*KDIM + kt*32 + c4*8);
        CP_COMMIT();
    };

    int lrow = lane & 15, lc = lane >> 4;
    uint32_t a_off[2], w_off[2][2];
    #pragma unroll
    for (int kh = 0; kh < 2; kh++) {
        int row = wid*16 + lrow;
        a_off[kh] = (uint32_t)(row*64 + (((kh*2 + lc) ^ ((row>>1)&3))*16));
        #pragma unroll
        for (int h = 0; h < 2; h++) {
            int wr2 = h*16 + lrow;
            w_off[h][kh] = (uint32_t)(wr2*64 + (((kh*2 + lc) ^ ((wr2>>1)&3))*16));
        }
    }

    float acc[4][4];
    #pragma unroll
    for (int i = 0; i < 4; i++)
        #pragma unroll
        for (int q = 0; q < 4; q++) acc[i][q] = 0.f;

    load_stage(0, 0); load_stage(1, 1); load_stage(2, 2);

    for (int kt = 0; kt < OC_NIT; kt++) {
        if (kt + 2 < OC_NIT) asm volatile("cp.async.wait_group 2;" ::: "memory");
        else                 asm volatile("cp.async.wait_group 0;" ::: "memory");
        __syncthreads();
        if (kt + 3 < OC_NIT) load_stage((kt+3) & 3, kt+3);

        uint32_t base = sb + (uint32_t)(kt & 3) * OC_STG;
        #pragma unroll
        for (int kh = 0; kh < 2; kh++) {
            uint32_t ah[4];
            LDSM4(ah, base + a_off[kh]);
            #pragma unroll
            for (int h = 0; h < 2; h++) {
                uint32_t wh[4];
                LDSM4(wh, base + 2048 + w_off[h][kh]);
                MMA16816(acc[h*2],   ah, wh[0], wh[2]);
                MMA16816(acc[h*2+1], ah, wh[1], wh[3]);
            }
        }
    }

    int rr = bm + wid*16 + (lane >> 2);
    #pragma unroll
    for (int nj = 0; nj < 4; nj++) {
        int col = (nj >> 1)*16 + (nj & 1)*8 + (lane & 3)*2;
        float b0v = offb[col], b1v = offb[col+1];
        *(float2*)&g_off[(size_t)rr*NOFF + col] =
            make_float2(acc[nj][0] + b0v, acc[nj][1] + b1v);
        *(float2*)&g_off[(size_t)(rr+8)*NOFF + col] =
            make_float2(acc[nj][2] + b0v, acc[nj][3] + b1v);
    }
}

// =====================================================================
// Kernel 4: bilinear sampling (fp16 src, half2 math) -> fp16 A
// R10-best form; launch_bounds(256,6) caps regs for occupancy.
// =====================================================================
__global__ __launch_bounds__(256, 6) void sample_kernel()
{
    int m    = (blockIdx.x*256 + threadIdx.x) >> 5;
    int lane = threadIdx.x & 31;
    int b = m / SPA, s = m % SPA;
    int oh = s / HO, ow = s % HO;

    int e00 = 0, e01 = 0, e10 = 0, e11 = 0;
    uint32_t uq00 = 0, uq01 = 0, uq10 = 0, uq11 = 0;
    if (lane < 16) {
        int k = lane;
        float offy = g_off[(size_t)m*NOFF + k*2];
        float offx = g_off[(size_t)m*NOFF + k*2 + 1];
        float py = (float)(oh*4 + (k >> 2)) + offy;
        float px = (float)(ow*4 + (k & 3)) + offx;
        float y0f = floorf(py), x0f = floorf(px);
        float wy = py - y0f, wx = px - x0f;
        int y0 = (int)y0f, x0 = (int)x0f;
        int y1 = y0 + 1,  x1 = x0 + 1;
        bool vy0 = (y0 >= 0) & (y0 < HH), vy1 = (y1 >= 0) & (y1 < HH);
        bool vx0 = (x0 >= 0) & (x0 < HH), vx1 = (x1 >= 0) & (x1 < HH);
        int cy0 = min(max(y0, 0), HH-1), cy1 = min(max(y1, 0), HH-1);
        int cx0 = min(max(x0, 0), HH-1), cx1 = min(max(x1, 0), HH-1);
        e00 = (cy0*HH + cx0)*CH;
        e01 = (cy0*HH + cx1)*CH;
        e10 = (cy1*HH + cx0)*CH;
        e11 = (cy1*HH + cx1)*CH;
        float w00 = (1.f-wy)*(1.f-wx) * (float)(vy0 && vx0);
        float w01 = (1.f-wy)*wx       * (float)(vy0 && vx1);
        float w10 = wy*(1.f-wx)       * (float)(vy1 && vx0);
        float w11 = wy*wx             * (float)(vy1 && vx1);
        __half2 h;
        h = __floats2half2_rn(w00, w00); uq00 = *(uint32_t*)&h;
        h = __floats2half2_rn(w01, w01); uq01 = *(uint32_t*)&h;
        h = __floats2half2_rn(w10, w10); uq10 = *(uint32_t*)&h;
        h = __floats2half2_rn(w11, w11); uq11 = *(uint32_t*)&h;
    }

    const __half* hb = g_hh + (size_t)b*HH*HH*CH;
    __half* ob = g_Af + (size_t)m*KDIM;
    int c = (lane < 12) ? lane*8 : 0;

    #pragma unroll 4
    for (int k = 0; k < 16; k++) {
        int f00 = __shfl_sync(0xFFFFFFFFu, e00, k);
        int f01 = __shfl_sync(0xFFFFFFFFu, e01, k);
        int f10 = __shfl_sync(0xFFFFFFFFu, e10, k);
        int f11 = __shfl_sync(0xFFFFFFFFu, e11, k);
        uint32_t p00 = __shfl_sync(0xFFFFFFFFu, uq00, k);
        uint32_t p01 = __shfl_sync(0xFFFFFFFFu, uq01, k);
        uint32_t p10 = __shfl_sync(0xFFFFFFFFu, uq10, k);
        uint32_t p11 = __shfl_sync(0xFFFFFFFFu, uq11, k);
        if (lane < 12) {
            __half2 q00 = *(__half2*)&p00, q01 = *(__half2*)&p01;
            __half2 q10 = *(__half2*)&p10, q11 = *(__half2*)&p11;
            uint4 u00 = *(const uint4*)(hb + f00 + c);
            uint4 u01 = *(const uint4*)(hb + f01 + c);
            uint4 u10 = *(const uint4*)(hb + f10 + c);
            uint4 u11 = *(const uint4*)(hb + f11 + c);
            const uint32_t* a4 = &u00.x;
            const uint32_t* b4 = &u01.x;
            const uint32_t* c4 = &u10.x;
            const uint32_t* d4 = &u11.x;
            uint4 o;
            uint32_t* o4 = &o.x;
            #pragma unroll
            for (int t = 0; t < 4; t++) {
                __half2 r = __hmul2(*(const __half2*)&a4[t], q00);
                r = __hfma2(*(const __half2*)&b4[t], q01, r);
                r = __hfma2(*(const __half2*)&c4[t], q10, r);
                r = __hfma2(*(const __half2*)&d4[t], q11, r);
                o4[t] = *(uint32_t*)&r;
            }
            *(uint4*)(ob + k*CH + c) = o;
        }
    }
}

// =====================================================================
// Kernel 5: single-pass fp16 GEMM + BN2 + LeakyReLU
// CTA 128x128, BK=64, 8 warps (warp 64x32), 3-stage cp.async, 2 CTA/SM
// (R8/R10 measured-best configuration; at the mma.sync MAC-rate ceiling)
// =====================================================================
#define BK       64
#define NIT      24
#define OFF_B    16384u
#define STG_BYTES 32768u
#define NSTAGE   3
#define SMEM_GEMM (NSTAGE*STG_BYTES + 1024)

__global__ __launch_bounds__(256, 2) void gemm_mma_kernel(
    const float* __restrict__ dcnb, const float* __restrict__ g2,
    const float* __restrict__ b2,   const float* __restrict__ bn2m,
    const float* __restrict__ v2,   float* __restrict__ out)
{
    extern __shared__ char smem[];
    uint32_t sb = smem_to_u32(smem);
    float* sScale = (float*)(smem + NSTAGE*STG_BYTES);
    float* sBeta  = sScale + 128;

    int tid  = threadIdx.x;
    int lane = tid & 31, wid = tid >> 5;
    int wm = wid & 1, wn = wid >> 1;
    int bm = blockIdx.y * 128;
    int bn = blockIdx.x * 128;

    if (tid < 128) {
        int n = bn + tid;
        float inv = g2[n] * rsqrtf(v2[n] + 1e-5f);
        sScale[tid] = inv;
        sBeta[tid]  = (dcnb[n] - bn2m[n])*inv + b2[n];
    }

    auto load_stage = [&](int stg, int kt) {
        uint32_t base = sb + (uint32_t)stg * STG_BYTES;
        int ks = kt * BK;
        #pragma unroll
        for (int i = 0; i < 4; i++) {
            int id = tid + i*256;
            int row = id >> 3, c = id & 7;
            uint32_t so = (uint32_t)(row*128 + ((c ^ (row & 7))*16));
            CP_ASYNC16(base + so, g_Af + (size_t)(bm+row)*KDIM + ks + c*8);
        }
        #pragma unroll
        for (int i = 0; i < 4; i++) {
            int id = tid + i*256;
            int row = id >> 3, c = id & 7;
            uint32_t so = (uint32_t)(row*128 + ((c ^ (row & 7))*16));
            CP_ASYNC16(base + OFF_B + so, g_Bhi + (size_t)(bn+row)*KDIM + ks + c*8);
        }
        CP_COMMIT();
    };

    int lrow = lane & 15, lc = lane >> 4;
    uint32_t a_base[4]; int a_rs[4];
    uint32_t b_base[2]; int b_rs[2];
    #pragma unroll
    for (int mi = 0; mi < 4; mi++) {
        int row = wm*64 + mi*16 + lrow;
        a_base[mi] = (uint32_t)(row*128);
        a_rs[mi]   = row & 7;
    }
    #pragma unroll
    for (int nb = 0; nb < 2; nb++) {
        int row = wn*32 + nb*16 + lrow;
        b_base[nb] = (uint32_t)(row*128);
        b_rs[nb]   = row & 7;
    }

    float acc[4][4][4];
    #pragma unroll
    for (int i = 0; i < 4; i++)
        #pragma unroll
        for (int j = 0; j < 4; j++)
            #pragma unroll
            for (int q = 0; q < 4; q++) acc[i][j][q] = 0.f;

    load_stage(0, 0); load_stage(1, 1);

    for (int kt = 0; kt < NIT; kt++) {
        if (kt + 1 < NIT) asm volatile("cp.async.wait_group 1;" ::: "memory");
        else              asm volatile("cp.async.wait_group 0;" ::: "memory");
        __syncthreads();
        if (kt + 2 < NIT) load_stage((kt+2) % NSTAGE, kt+2);

        uint32_t base = sb + (uint32_t)(kt % NSTAGE) * STG_BYTES;
        #pragma unroll
        for (int kh = 0; kh < 4; kh++) {
            int ch = kh*2 + lc;
            uint32_t a[4][4];
            #pragma unroll
            for (int mi = 0; mi < 4; mi++)
                LDSM4(a[mi], base + a_base[mi] + (uint32_t)(((ch ^ a_rs[mi]) << 4)));
            #pragma unroll
            for (int nb = 0; nb < 2; nb++) {
                uint32_t bh[4];
                LDSM4(bh, base + OFF_B + b_base[nb] + (uint32_t)(((ch ^ b_rs[nb]) << 4)));
                #pragma unroll
                for (int mi = 0; mi < 4; mi++) {
                    MMA16816(acc[mi][2*nb],   a[mi], bh[0], bh[2]);
                    MMA16816(acc[mi][2*nb+1], a[mi], bh[1], bh[3]);
                }
            }
        }
    }

    #pragma unroll
    for (int mi = 0; mi < 4; mi++) {
        int r0 = bm + wm*64 + mi*16 + (lane >> 2);
        #pragma unroll
        for (int nj = 0; nj < 4; nj++) {
            int colL = wn*32 + nj*8 + (lane & 3)*2;
            float s0 = sScale[colL],   s1 = sScale[colL+1];
            float e0 = sBeta[colL],    e1 = sBeta[colL+1];
            float v0 = acc[mi][nj][0]*s0 + e0;
            float v1 = acc[mi][nj][1]*s1 + e1;
            float v2 = acc[mi][nj][2]*s0 + e0;
            float v3 = acc[mi][nj][3]*s1 + e1;
            v0 = (v0 >= 0.f) ? v0 : 0.01f*v0;
            v1 = (v1 >= 0.f) ? v1 : 0.01f*v1;
            v2 = (v2 >= 0.f) ? v2 : 0.01f*v2;
            v3 = (v3 >= 0.f) ? v3 : 0.01f*v3;
            *(float2*)&out[(size_t)r0*ND + bn + colL]     = make_float2(v0, v1);
            *(float2*)&out[(size_t)(r0+8)*ND + bn + colL] = make_float2(v2, v3);
        }
    }
}

// =====================================================================
extern "C" void kernel_launch(void* const* d_in, const int* in_sizes, int n_in,
                              void* d_out, int out_size)
{
    const float* x      = (const float*)d_in[0];
    const float* stem_w = (const float*)d_in[1];
    const float* stem_b = (const float*)d_in[2];
    const float* bn1_g  = (const float*)d_in[3];
    const float* bn1_b  = (const float*)d_in[4];
    const float* bn1_m  = (const float*)d_in[5];
    const float* bn1_v  = (const float*)d_in[6];
    const float* off_w  = (const float*)d_in[7];
    const float* off_b  = (const float*)d_in[8];
    const float* dcn_w  = (const float*)d_in[9];
    const float* dcn_b  = (const float*)d_in[10];
    const float* bn2_g  = (const float*)d_in[11];
    const float* bn2_b  = (const float*)d_in[12];
    const float* bn2_m  = (const float*)d_in[13];
    const float* bn2_v  = (const float*)d_in[14];
    float* out = (float*)d_out;

    cudaFuncSetAttribute(gemm_mma_kernel,
                         cudaFuncAttributeMaxDynamicSharedMemorySize, SMEM_GEMM);
    cudaFuncSetAttribute(offconv_mma_kernel,
                         cudaFuncAttributeMaxDynamicSharedMemorySize, SMEM_OC);
    cudaFuncSetAttribute(stem_mma_kernel,
                         cudaFuncAttributeMaxDynamicSharedMemorySize, SMEM_ST);

    stem_mma_kernel<<<NSTEM + PREP_BLKS, 128, SMEM_ST>>>(
        x, stem_w, stem_b, bn1_g, bn1_b, bn1_m, bn1_v, dcn_w, off_w);
    offconv_mma_kernel<<<MM2/32, 64, SMEM_OC>>>(off_b);
    sample_kernel<<<MM2*32/256, 256>>>();
    gemm_mma_kernel<<<dim3(ND/128, MM2/128), 256, SMEM_GEMM>>>(
        dcn_b, bn2_g, bn2_b, bn2_m, bn2_v, out);
}